// round 6
// baseline (speedup 1.0000x reference)
#include <cuda_runtime.h>

// Problem constants (fixed shapes from reference):
//   x : (2, 128, 96, 96) f32, w{q,k,v} : (4, 32, 32) f32
//   K = 5 window, reflect pad 2, G = 4 groups of 32 channels.
#define BB   2
#define GG   4
#define CIN  32
#define CON  32
#define HHN  96
#define WWN  96
#define HWSZ (HHN * WWN)
#define CTOT 128

// Scratch for the three 1x1-conv outputs (q, k, v), each (B, 128, 96, 96).
__device__ __align__(256) float g_q[BB * CTOT * HWSZ];
__device__ __align__(256) float g_k[BB * CTOT * HWSZ];
__device__ __align__(256) float g_v[BB * CTOT * HWSZ];

// -----------------------------------------------------------------------------
// Kernel A: grouped 1x1 convs (q, k, v) fused — one CTA per (b, g, h) row.
// Accumulators held as packed f32x2 pairs; the mainloop uses fma.rn.f32x2
// (FFMA2) so each issue retires 2 fp32 FMAs — halves the fma-pipe demand vs
// scalar FFMA (3-reg FFMA has rt_SMSP=2). Bit-exact fp32 per lane.
// -----------------------------------------------------------------------------
__global__ __launch_bounds__(256, 2) void qkv_kernel(
    const float* __restrict__ x,
    const float* __restrict__ wq,
    const float* __restrict__ wk,
    const float* __restrict__ wv)
{
    __shared__ float xs[CIN * WWN];            // 12 KB
    __shared__ float wqs[CON * 33];            // padded stride 33
    __shared__ float wks[CON * 33];
    __shared__ float wvs[CON * 33];

    const int h   = blockIdx.x;
    const int bg  = blockIdx.y;                // b*G + g
    const int g   = bg & (GG - 1);
    const int tid = threadIdx.x;

    // Stage x row with float4 loads: x[bg*32 + i][h][w]
    const float* xbase = x + (size_t)bg * CIN * HWSZ + (size_t)h * WWN;
    #pragma unroll
    for (int idx = tid; idx < CIN * (WWN / 4); idx += 256) {
        int i  = idx / (WWN / 4);
        int w4 = idx - i * (WWN / 4);
        reinterpret_cast<float4*>(xs)[i * (WWN / 4) + w4] =
            reinterpret_cast<const float4*>(xbase + (size_t)i * HWSZ)[w4];
    }
    // Stage weights of this group
    const float* wqg = wq + (size_t)g * CON * CIN;
    const float* wkg = wk + (size_t)g * CON * CIN;
    const float* wvg = wv + (size_t)g * CON * CIN;
    #pragma unroll
    for (int idx = tid; idx < CON * CIN; idx += 256) {
        int o = idx >> 5;
        int i = idx & 31;
        wqs[o * 33 + i] = wqg[idx];
        wks[o * 33 + i] = wkg[idx];
        wvs[o * 33 + i] = wvg[idx];
    }
    __syncthreads();

    const int o    = tid >> 3;            // 0..31 output channel
    const int wseg = (tid & 7) * 12;      // 12 consecutive w positions

    unsigned long long aq[6], ak[6], av[6];   // 6 f32x2 pairs each
    #pragma unroll
    for (int u = 0; u < 6; u++) { aq[u] = 0ull; ak[u] = 0ull; av[u] = 0ull; }

    #pragma unroll 8
    for (int i = 0; i < CIN; i++) {
        const float wqv = wqs[o * 33 + i];
        const float wkv = wks[o * 33 + i];
        const float wvv = wvs[o * 33 + i];
        unsigned long long wq2, wk2, wv2;
        asm("mov.b64 %0, {%1, %1};" : "=l"(wq2) : "f"(wqv));
        asm("mov.b64 %0, {%1, %1};" : "=l"(wk2) : "f"(wkv));
        asm("mov.b64 %0, {%1, %1};" : "=l"(wv2) : "f"(wvv));

        const float4* xv = reinterpret_cast<const float4*>(&xs[i * WWN + wseg]);
        union { float4 f; unsigned long long u[2]; } x0, x1, x2;
        x0.f = xv[0]; x1.f = xv[1]; x2.f = xv[2];
        unsigned long long xp[6] = { x0.u[0], x0.u[1], x1.u[0], x1.u[1],
                                     x2.u[0], x2.u[1] };
        #pragma unroll
        for (int u = 0; u < 6; u++) {
            asm("fma.rn.f32x2 %0, %1, %2, %0;" : "+l"(aq[u]) : "l"(xp[u]), "l"(wq2));
            asm("fma.rn.f32x2 %0, %1, %2, %0;" : "+l"(ak[u]) : "l"(xp[u]), "l"(wk2));
            asm("fma.rn.f32x2 %0, %1, %2, %0;" : "+l"(av[u]) : "l"(xp[u]), "l"(wv2));
        }
    }

    const size_t obase = (size_t)(bg * CON + o) * HWSZ + (size_t)h * WWN + wseg;
    float4* qo = reinterpret_cast<float4*>(&g_q[obase]);
    float4* ko = reinterpret_cast<float4*>(&g_k[obase]);
    float4* vo = reinterpret_cast<float4*>(&g_v[obase]);
    #pragma unroll
    for (int u = 0; u < 3; u++) {
        union { unsigned long long u2[2]; float4 f; } rq, rk, rv;
        rq.u2[0] = aq[2*u]; rq.u2[1] = aq[2*u+1];
        rk.u2[0] = ak[2*u]; rk.u2[1] = ak[2*u+1];
        rv.u2[0] = av[2*u]; rv.u2[1] = av[2*u+1];
        qo[u] = rq.f;
        ko[u] = rk.f;
        vo[u] = rv.f;
    }
}

// -----------------------------------------------------------------------------
// Kernel B: per-channel 5x5 windowed softmax with reflect indexing.
// One CTA = 32x32 spatial tile x 1 channel. Each thread computes 4 consecutive
// w outputs: adjacent windows share 4/5 columns, so only 8 k + 8 v smem loads
// per window row serve 4 outputs (20 LDS/output).
// Halo stride 41 (== 9 mod 32): bank = 9*ty + 4*tx + j is a permutation over
// the warp's 4(ty) x 8(tx) layout -> conflict-free scalar LDS.
// Single-pass softmax via raw ex2.approx (log2e folded into q). MUFU-bound.
// -----------------------------------------------------------------------------
__device__ __forceinline__ int refl(int i, int n) {
    return i < 0 ? -i : (i >= n ? 2 * n - 2 - i : i);
}

__device__ __forceinline__ float ex2(float x) {
    float y;
    asm("ex2.approx.ftz.f32 %0, %1;" : "=f"(y) : "f"(x));
    return y;
}

#define HALO 36
#define HSTR 41

__global__ __launch_bounds__(256) void attn_kernel(float* __restrict__ out)
{
    __shared__ float ks[HALO * HSTR];   // 5.9 KB
    __shared__ float vs[HALO * HSTR];

    const int ch  = blockIdx.z;               // 0..255 = b*128 + channel
    const int h0  = blockIdx.y * 32;
    const int w0  = blockIdx.x * 32;
    const int tid = threadIdx.x;
    const int tx  = tid & 7;                  // 8 threads across w (4 outputs each)
    const int ty  = tid >> 3;                 // 32 rows

    const size_t cbase = (size_t)ch * HWSZ;

    // Stage k/v halos (36x36 window, reflect at global borders).
    #pragma unroll
    for (int idx = tid; idx < HALO * HALO; idx += 256) {
        int r  = idx / HALO;
        int c  = idx - r * HALO;
        int hh = refl(h0 - 2 + r, HHN);
        int ww = refl(w0 - 2 + c, WWN);
        size_t gi = cbase + (size_t)hh * WWN + ww;
        ks[r * HSTR + c] = g_k[gi];
        vs[r * HSTR + c] = g_v[gi];
    }
    __syncthreads();

    const int h    = h0 + ty;
    const int wsub = tx * 4;                  // halo column base for this thread
    const size_t pix = (size_t)h * WWN + (w0 + wsub);

    const float4 q4 = *reinterpret_cast<const float4*>(&g_q[cbase + pix]);
    const float L2E = 1.44269504088896341f;
    float ql2[4] = { q4.x * L2E, q4.y * L2E, q4.z * L2E, q4.w * L2E };

    float num[4] = {0.f, 0.f, 0.f, 0.f};
    float den[4] = {0.f, 0.f, 0.f, 0.f};

    #pragma unroll
    for (int r = 0; r < 5; r++) {
        const float* kp = &ks[(ty + r) * HSTR + wsub];
        const float* vp = &vs[(ty + r) * HSTR + wsub];
        float kk[8], vv[8];
        #pragma unroll
        for (int j = 0; j < 8; j++) { kk[j] = kp[j]; vv[j] = vp[j]; }
        #pragma unroll
        for (int o = 0; o < 4; o++) {
            #pragma unroll
            for (int c = 0; c < 5; c++) {
                float e = ex2(ql2[o] * kk[o + c]);
                den[o] += e;
                num[o] = fmaf(e, vv[o + c], num[o]);
            }
        }
    }

    float4 r4 = make_float4(__fdividef(num[0], den[0]),
                            __fdividef(num[1], den[1]),
                            __fdividef(num[2], den[2]),
                            __fdividef(num[3], den[3]));
    *reinterpret_cast<float4*>(&out[cbase + pix]) = r4;
}

// -----------------------------------------------------------------------------
// Launch: two kernels, graph-capturable (no sync, no alloc).
// Inputs (metadata order): x, wq, wk, wv — all float32. Output float32.
// -----------------------------------------------------------------------------
extern "C" void kernel_launch(void* const* d_in, const int* in_sizes, int n_in,
                              void* d_out, int out_size)
{
    const float* x  = (const float*)d_in[0];
    const float* wq = (const float*)d_in[1];
    const float* wk = (const float*)d_in[2];
    const float* wv = (const float*)d_in[3];
    float* out = (float*)d_out;

    qkv_kernel<<<dim3(HHN, BB * GG), 256>>>(x, wq, wk, wv);
    attn_kernel<<<dim3(WWN / 32, HHN / 32, BB * CTOT), dim3(256)>>>(out);
}

// round 7
// speedup vs baseline: 1.0060x; 1.0060x over previous
#include <cuda_runtime.h>

// Problem constants (fixed shapes from reference):
//   x : (2, 128, 96, 96) f32, w{q,k,v} : (4, 32, 32) f32
//   K = 5 window, reflect pad 2, G = 4 groups of 32 channels.
#define BB   2
#define GG   4
#define CIN  32
#define CON  32
#define HHN  96
#define WWN  96
#define HWSZ (HHN * WWN)
#define CTOT 128

// Scratch for the three 1x1-conv outputs (q, k, v), each (B, 128, 96, 96).
__device__ __align__(256) float g_q[BB * CTOT * HWSZ];
__device__ __align__(256) float g_k[BB * CTOT * HWSZ];
__device__ __align__(256) float g_v[BB * CTOT * HWSZ];

// -----------------------------------------------------------------------------
// Kernel A: grouped 1x1 convs (q, k, v) fused — one CTA per (b, g, h) row.
// Mainloop: packed fma.rn.f32x2 accumulators (2 fp32 FMA per issue, exact).
// Epilogue: accumulators bounce through a padded smem tile so global stores
// are lane-consecutive full 128-B lines (the direct store pattern wrote 16-B
// chunks at 48-B stride across 4 distant rows -> partial-sector writes were
// the real qkv bottleneck).
// -----------------------------------------------------------------------------
#define OSTR 100   // epilogue smem row stride in floats (float4 stride 25)

__global__ __launch_bounds__(256) void qkv_kernel(
    const float* __restrict__ x,
    const float* __restrict__ wq,
    const float* __restrict__ wk,
    const float* __restrict__ wv)
{
    __shared__ float xs[CIN * WWN];            // 12 KB input row tile
    __shared__ float os[CON * OSTR];           // 12.8 KB epilogue bounce buffer
    __shared__ float wqs[CON * 33];            // padded stride 33
    __shared__ float wks[CON * 33];
    __shared__ float wvs[CON * 33];

    const int h   = blockIdx.x;
    const int bg  = blockIdx.y;                // b*G + g
    const int g   = bg & (GG - 1);
    const int tid = threadIdx.x;

    // Stage x row with float4 loads: x[bg*32 + i][h][w]
    const float* xbase = x + (size_t)bg * CIN * HWSZ + (size_t)h * WWN;
    #pragma unroll
    for (int idx = tid; idx < CIN * (WWN / 4); idx += 256) {
        int i  = idx / (WWN / 4);
        int w4 = idx - i * (WWN / 4);
        reinterpret_cast<float4*>(xs)[i * (WWN / 4) + w4] =
            reinterpret_cast<const float4*>(xbase + (size_t)i * HWSZ)[w4];
    }
    // Stage weights of this group
    const float* wqg = wq + (size_t)g * CON * CIN;
    const float* wkg = wk + (size_t)g * CON * CIN;
    const float* wvg = wv + (size_t)g * CON * CIN;
    #pragma unroll
    for (int idx = tid; idx < CON * CIN; idx += 256) {
        int o = idx >> 5;
        int i = idx & 31;
        wqs[o * 33 + i] = wqg[idx];
        wks[o * 33 + i] = wkg[idx];
        wvs[o * 33 + i] = wvg[idx];
    }
    __syncthreads();

    const int o    = tid >> 3;            // 0..31 output channel
    const int wseg = (tid & 7) * 12;      // 12 consecutive w positions

    unsigned long long aq[6], ak[6], av[6];   // 6 f32x2 pairs each
    #pragma unroll
    for (int u = 0; u < 6; u++) { aq[u] = 0ull; ak[u] = 0ull; av[u] = 0ull; }

    #pragma unroll 8
    for (int i = 0; i < CIN; i++) {
        const float wqv = wqs[o * 33 + i];
        const float wkv = wks[o * 33 + i];
        const float wvv = wvs[o * 33 + i];
        unsigned long long wq2, wk2, wv2;
        asm("mov.b64 %0, {%1, %1};" : "=l"(wq2) : "f"(wqv));
        asm("mov.b64 %0, {%1, %1};" : "=l"(wk2) : "f"(wkv));
        asm("mov.b64 %0, {%1, %1};" : "=l"(wv2) : "f"(wvv));

        const float4* xv = reinterpret_cast<const float4*>(&xs[i * WWN + wseg]);
        union { float4 f; unsigned long long u[2]; } x0, x1, x2;
        x0.f = xv[0]; x1.f = xv[1]; x2.f = xv[2];
        unsigned long long xp[6] = { x0.u[0], x0.u[1], x1.u[0], x1.u[1],
                                     x2.u[0], x2.u[1] };
        #pragma unroll
        for (int u = 0; u < 6; u++) {
            asm("fma.rn.f32x2 %0, %1, %2, %0;" : "+l"(aq[u]) : "l"(xp[u]), "l"(wq2));
            asm("fma.rn.f32x2 %0, %1, %2, %0;" : "+l"(ak[u]) : "l"(xp[u]), "l"(wk2));
            asm("fma.rn.f32x2 %0, %1, %2, %0;" : "+l"(av[u]) : "l"(xp[u]), "l"(wv2));
        }
    }

    // ---- Epilogue: smem transpose-bounce for fully coalesced global stores.
    const size_t rowbase = (size_t)(bg * CON) * HWSZ + (size_t)h * WWN;
    float4* osv = reinterpret_cast<float4*>(os);

    unsigned long long* accs[3] = { aq, ak, av };
    float* gouts[3] = { g_q + rowbase, g_k + rowbase, g_v + rowbase };

    #pragma unroll
    for (int t = 0; t < 3; t++) {
        if (t) __syncthreads();               // previous copy-out done
        // scatter accumulators into padded smem tile (STS.128, <=4-way)
        unsigned long long* a = accs[t];
        #pragma unroll
        for (int u = 0; u < 3; u++) {
            union { unsigned long long u2[2]; float4 f; } r;
            r.u2[0] = a[2*u]; r.u2[1] = a[2*u+1];
            osv[o * (OSTR / 4) + (wseg / 4) + u] = r.f;
        }
        __syncthreads();
        // copy out: lane-consecutive float4 across each channel row
        float* gout = gouts[t];
        #pragma unroll
        for (int idx = tid; idx < CON * (WWN / 4); idx += 256) {
            int oc = idx / (WWN / 4);
            int w4 = idx - oc * (WWN / 4);
            reinterpret_cast<float4*>(gout + (size_t)oc * HWSZ)[w4] =
                osv[oc * (OSTR / 4) + w4];
        }
    }
}

// -----------------------------------------------------------------------------
// Kernel B: per-channel 5x5 windowed softmax with reflect indexing.
// One CTA = 32x32 spatial tile x 1 channel. Each thread computes 4 consecutive
// w outputs (adjacent windows share 4/5 columns -> 20 LDS/output).
// Halo stride 41 keeps scalar LDS conflict-free. Single-pass softmax via raw
// ex2.approx (log2e folded into q). MUFU-bound at ~13us chip floor.
// -----------------------------------------------------------------------------
__device__ __forceinline__ int refl(int i, int n) {
    return i < 0 ? -i : (i >= n ? 2 * n - 2 - i : i);
}

__device__ __forceinline__ float ex2(float x) {
    float y;
    asm("ex2.approx.ftz.f32 %0, %1;" : "=f"(y) : "f"(x));
    return y;
}

#define HALO 36
#define HSTR 41

__global__ __launch_bounds__(256) void attn_kernel(float* __restrict__ out)
{
    __shared__ float ks[HALO * HSTR];   // 5.9 KB
    __shared__ float vs[HALO * HSTR];

    const int ch  = blockIdx.z;               // 0..255 = b*128 + channel
    const int h0  = blockIdx.y * 32;
    const int w0  = blockIdx.x * 32;
    const int tid = threadIdx.x;
    const int tx  = tid & 7;                  // 8 threads across w (4 outputs each)
    const int ty  = tid >> 3;                 // 32 rows

    const size_t cbase = (size_t)ch * HWSZ;

    // Stage k/v halos (36x36 window, reflect at global borders).
    #pragma unroll
    for (int idx = tid; idx < HALO * HALO; idx += 256) {
        int r  = idx / HALO;
        int c  = idx - r * HALO;
        int hh = refl(h0 - 2 + r, HHN);
        int ww = refl(w0 - 2 + c, WWN);
        size_t gi = cbase + (size_t)hh * WWN + ww;
        ks[r * HSTR + c] = g_k[gi];
        vs[r * HSTR + c] = g_v[gi];
    }
    __syncthreads();

    const int h    = h0 + ty;
    const int wsub = tx * 4;                  // halo column base for this thread
    const size_t pix = (size_t)h * WWN + (w0 + wsub);

    const float4 q4 = *reinterpret_cast<const float4*>(&g_q[cbase + pix]);
    const float L2E = 1.44269504088896341f;
    float ql2[4] = { q4.x * L2E, q4.y * L2E, q4.z * L2E, q4.w * L2E };

    float num[4] = {0.f, 0.f, 0.f, 0.f};
    float den[4] = {0.f, 0.f, 0.f, 0.f};

    #pragma unroll
    for (int r = 0; r < 5; r++) {
        const float* kp = &ks[(ty + r) * HSTR + wsub];
        const float* vp = &vs[(ty + r) * HSTR + wsub];
        float kk[8], vv[8];
        #pragma unroll
        for (int j = 0; j < 8; j++) { kk[j] = kp[j]; vv[j] = vp[j]; }
        #pragma unroll
        for (int o = 0; o < 4; o++) {
            #pragma unroll
            for (int c = 0; c < 5; c++) {
                float e = ex2(ql2[o] * kk[o + c]);
                den[o] += e;
                num[o] = fmaf(e, vv[o + c], num[o]);
            }
        }
    }

    float4 r4 = make_float4(__fdividef(num[0], den[0]),
                            __fdividef(num[1], den[1]),
                            __fdividef(num[2], den[2]),
                            __fdividef(num[3], den[3]));
    *reinterpret_cast<float4*>(&out[cbase + pix]) = r4;
}

// -----------------------------------------------------------------------------
// Launch: two kernels, graph-capturable (no sync, no alloc).
// Inputs (metadata order): x, wq, wk, wv — all float32. Output float32.
// -----------------------------------------------------------------------------
extern "C" void kernel_launch(void* const* d_in, const int* in_sizes, int n_in,
                              void* d_out, int out_size)
{
    const float* x  = (const float*)d_in[0];
    const float* wq = (const float*)d_in[1];
    const float* wk = (const float*)d_in[2];
    const float* wv = (const float*)d_in[3];
    float* out = (float*)d_out;

    qkv_kernel<<<dim3(HHN, BB * GG), 256>>>(x, wq, wk, wv);
    attn_kernel<<<dim3(WWN / 32, HHN / 32, BB * CTOT), dim3(256)>>>(out);
}